// round 11
// baseline (speedup 1.0000x reference)
#include <cuda_runtime.h>
#include <cuda_bf16.h>
#include <cstdint>

// ---------------------------------------------------------------------------
// HardNegativeMiner: bit-exact replication of jax.random, PARTITIONABLE
// threefry mode (JAX default):
//   split(key,n):  key_i  = threefry(key, (0, i))          (fold_in form)
//   bits32 at flat index i = out0 ^ out1 of threefry(key, 0, i)
//   randint(key,...): k1,k2 = split(key); span=2^14 power of two ->
//                     result = bits32(k2, j) & 0x3FFF       (int32, x64 off)
//   B=16384, D=256, n_hard=3276, TEMPERATURE=0.1, MIX_ALPHA=0.5
// ---------------------------------------------------------------------------

#define B_N   16384
#define D_K   256
#define NHARD 3276
#define RPB   24                // rows per block in the argmax kernel
#define NBLK  137               // ceil(3276 / 24)

// ------------------- scratch (static device memory only) -------------------
__device__ float g_znT[D_K * B_N];   // z_norm transposed: [k][c]  (16 MB)
__device__ int   g_src[NHARD];
__device__ int   g_tgt[NHARD];
__device__ float g_alpha[NHARD];

// ---------------- compile-time threefry for key derivation -----------------
struct U2c { unsigned a, b; };
constexpr unsigned rotl32c(unsigned v, int d) { return (v << d) | (v >> (32 - d)); }
constexpr U2c tf_const(unsigned k0, unsigned k1, unsigned x0, unsigned x1) {
    unsigned ks[3] = { k0, k1, k0 ^ k1 ^ 0x1BD11BDAu };
    x0 += ks[0]; x1 += ks[1];
    const int rotA[4] = {13, 15, 26, 6};
    const int rotB[4] = {17, 29, 16, 24};
    for (int g = 0; g < 5; ++g) {
        const int* R = (g % 2 == 0) ? rotA : rotB;
        for (int i = 0; i < 4; ++i) { x0 += x1; x1 = rotl32c(x1, R[i]); x1 ^= x0; }
        x0 += ks[(g + 1) % 3];
        x1 += ks[(g + 2) % 3] + (unsigned)(g + 1);
    }
    return U2c{ x0, x1 };
}
// jax.random.key(42) -> (0,42). Partitionable split: key_i = tf(key, 0, i).
constexpr U2c KSRC = tf_const(0u, 42u, 0u, 0u);   // k_src   = split(key,3)[0]
constexpr U2c KTGT = tf_const(0u, 42u, 0u, 1u);   // k_tgt   = split(key,3)[1]
constexpr U2c KALP = tf_const(0u, 42u, 0u, 2u);   // k_alpha = split(key,3)[2]
// randint's INTERNAL split: k1,k2 = split(k_src); lower_bits uses k2.
constexpr U2c KSL  = tf_const(KSRC.a, KSRC.b, 0u, 1u);
constexpr unsigned KL0 = KSL.a,  KL1 = KSL.b;     // randint lower-bits key
constexpr unsigned KT0 = KTGT.a, KT1 = KTGT.b;
constexpr unsigned KA0 = KALP.a, KA1 = KALP.b;

// ------------------------- device threefry2x32-20 --------------------------
__device__ __forceinline__ uint2 tf2x32(unsigned k0, unsigned k1,
                                        unsigned x0, unsigned x1) {
    unsigned k2 = k0 ^ k1 ^ 0x1BD11BDAu;
    x0 += k0; x1 += k1;
#define TF_R4(a,b,c,d) \
    x0 += x1; x1 = __funnelshift_l(x1, x1, a); x1 ^= x0; \
    x0 += x1; x1 = __funnelshift_l(x1, x1, b); x1 ^= x0; \
    x0 += x1; x1 = __funnelshift_l(x1, x1, c); x1 ^= x0; \
    x0 += x1; x1 = __funnelshift_l(x1, x1, d); x1 ^= x0;
    TF_R4(13,15,26,6);   x0 += k1; x1 += k2 + 1u;
    TF_R4(17,29,16,24);  x0 += k2; x1 += k0 + 2u;
    TF_R4(13,15,26,6);   x0 += k0; x1 += k1 + 3u;
    TF_R4(17,29,16,24);  x0 += k1; x1 += k2 + 4u;
    TF_R4(13,15,26,6);   x0 += k2; x1 += k0 + 5u;
#undef TF_R4
    return make_uint2(x0, x1);
}
// partitionable 32-bit random bits at flat index i (hi word of 64-bit iota = 0)
__device__ __forceinline__ unsigned bits32(unsigned k0, unsigned k1, unsigned i) {
    uint2 o = tf2x32(k0, k1, 0u, i);
    return o.x ^ o.y;
}

// ---------------- accurate logf (cephes, fast-math-immune) -----------------
// valid for positive normal inputs (all our inputs are in (5.9e-8, 88.8])
__device__ __forceinline__ float alog(float x) {
    int ix = __float_as_int(x);
    int e  = ((ix >> 23) & 0xff) - 126;
    float m = __int_as_float((ix & 0x007fffff) | 0x3f000000);  // [0.5, 1)
    if (m < 0.70710678f) { m = m + m; e -= 1; }                // [~0.707, ~1.414)
    float u = m - 1.0f;
    float z = u * u;
    float p =             7.0376836292e-2f;
    p = fmaf(p, u, -1.1514610310e-1f);
    p = fmaf(p, u,  1.1676998740e-1f);
    p = fmaf(p, u, -1.2420140846e-1f);
    p = fmaf(p, u,  1.4249322787e-1f);
    p = fmaf(p, u, -1.6668057665e-1f);
    p = fmaf(p, u,  2.0000714765e-1f);
    p = fmaf(p, u, -2.4999993993e-1f);
    p = fmaf(p, u,  3.3333331174e-1f);
    float y  = u * z * p;
    float fe = (float)e;
    y = fmaf(fe, -2.12194440e-4f, y);
    y = fmaf(-0.5f, z, y);
    float r = u + y;
    r = fmaf(fe, 0.693359375f, r);
    return r;
}

// uniform bits -> float in [0,1): jax mantissa trick
__device__ __forceinline__ float u01(unsigned bits) {
    return __uint_as_float((bits >> 9) | 0x3f800000u) - 1.0f;
}
// gumbel: -log(-log(max(tiny, u)))   (tiny = FLT_MIN; matches jax uniform clamp)
__device__ __forceinline__ float gumbel1(unsigned bits) {
    float f = u01(bits);
    float u = fmaxf(f, 1.17549435e-38f);
    float t = -alog(u);
    return -alog(t);
}

// --------------------------- f32x2 packed FMA ------------------------------
__device__ __forceinline__ unsigned long long pk(float lo, float hi) {
    unsigned long long r;
    asm("mov.b64 %0, {%1, %2};" : "=l"(r) : "f"(lo), "f"(hi));
    return r;
}
__device__ __forceinline__ float2 upk(unsigned long long v) {
    float2 f;
    asm("mov.b64 {%0, %1}, %2;" : "=f"(f.x), "=f"(f.y) : "l"(v));
    return f;
}
__device__ __forceinline__ void ffma2(unsigned long long& d,
                                      unsigned long long a,
                                      unsigned long long b) {
    asm("fma.rn.f32x2 %0, %1, %2, %0;" : "+l"(d) : "l"(a), "l"(b));
}

// ===========================================================================
// Kernel 1: L2-normalize rows of z, store TRANSPOSED -> g_znT[k][c]
// ===========================================================================
__global__ void k_norm(const float* __restrict__ z) {
    int c = blockIdx.x, t = threadIdx.x;
    float v  = z[c * D_K + t];
    float ss = v * v;
#pragma unroll
    for (int o = 16; o; o >>= 1) ss += __shfl_xor_sync(0xffffffffu, ss, o);
    __shared__ float sr[8];
    if ((t & 31) == 0) sr[t >> 5] = ss;
    __syncthreads();
    float tot = sr[0] + sr[1] + sr[2] + sr[3] + sr[4] + sr[5] + sr[6] + sr[7];
    float nrm = fmaxf(sqrtf(tot), 1e-12f);
    g_znT[t * B_N + c] = __fdiv_rn(v, nrm);
}

// ===========================================================================
// Kernel 2: src indices (randint int32 w/ internal split) + alpha (f32 * 0.5)
//   src[j]  = bits32(k2_src, j) & 0x3FFF   (multiplier degenerates to 0)
//   alpha[j]= u01(bits32(k_alpha, j)) * 0.5
// ===========================================================================
__global__ void k_rng() {
    int j = blockIdx.x * 256 + threadIdx.x;
    if (j < NHARD) {
        g_src[j]   = (int)(bits32(KL0, KL1, (unsigned)j) & (B_N - 1));
        g_alpha[j] = u01(bits32(KA0, KA1, (unsigned)j)) * 0.5f;
    }
}

// ===========================================================================
// Kernel 3: per sampled row j, tgt[j] = argmax_c [ gumbel(j,c) + sim(src_j,c)/0.1 ]
//   24 rows per block; A-rows broadcast from smem (LDS.128); columns streamed
//   coalesced from transposed z_norm; packed f32x2 FMA mainloop.
//   gumbel(j,c) bits = xor-fold threefry(k_tgt, 0, j*16384 + c).
// ===========================================================================
__global__ void __launch_bounds__(256, 1) k_argmax() {
    __shared__ __align__(16) float sA[RPB * 256];   // 24 KB A-tile
    __shared__ int   s_src[RPB];
    __shared__ float redV[RPB][8];
    __shared__ int   redC[RPB][8];

    const int tid  = threadIdx.x;
    const int lane = tid & 31, w = tid >> 5;
    const int jb = blockIdx.x * RPB;
    const int nrows = min(RPB, NHARD - jb);

    if (tid < RPB) s_src[tid] = (tid < nrows) ? g_src[jb + tid] : 0;
    __syncthreads();

    // fill A-tile: row r = z_norm[src_{jb+r}] (gathered from transposed layout)
#pragma unroll 1
    for (int r = 0; r < RPB; ++r)
        sA[r * 256 + tid] = g_znT[tid * B_N + s_src[r]];
    __syncthreads();

    const ulonglong2* sAv = reinterpret_cast<const ulonglong2*>(sA);

    float bestV[RPB]; int bestC[RPB];
#pragma unroll
    for (int r = 0; r < RPB; ++r) { bestV[r] = __int_as_float(0xff800000); bestC[r] = 0; }

    for (int it = 0; it < 32; ++it) {
        const int c0 = it * 512 + w * 64 + lane;   // lanes -> consecutive cols
        const int c1 = c0 + 32;

        unsigned long long acc[2 * RPB];            // [row][col 0..1]
#pragma unroll
        for (int i = 0; i < 2 * RPB; ++i) acc[i] = 0ull;

        const float* pb0 = g_znT + c0;
        const float* pb1 = g_znT + c1;

#pragma unroll 2
        for (int kc = 0; kc < 64; ++kc) {          // 4 k per chunk
            float x0 = pb0[0], x1 = pb0[B_N], x2 = pb0[2 * B_N], x3 = pb0[3 * B_N];
            float y0 = pb1[0], y1 = pb1[B_N], y2 = pb1[2 * B_N], y3 = pb1[3 * B_N];
            pb0 += 4 * B_N; pb1 += 4 * B_N;
            unsigned long long bl0 = pk(x0, x1), bh0 = pk(x2, x3);
            unsigned long long bl1 = pk(y0, y1), bh1 = pk(y2, y3);
#pragma unroll
            for (int r = 0; r < RPB; ++r) {
                ulonglong2 a = sAv[r * 64 + kc];   // LDS.128 broadcast
                ffma2(acc[2 * r + 0], a.x, bl0);
                ffma2(acc[2 * r + 0], a.y, bh0);
                ffma2(acc[2 * r + 1], a.x, bl1);
                ffma2(acc[2 * r + 1], a.y, bh1);
            }
        }

        // epilogue: gumbel + logits, running argmax
#pragma unroll
        for (int r = 0; r < RPB; ++r) {
            unsigned base = (unsigned)(jb + r) * (unsigned)B_N;
#pragma unroll
            for (int cc = 0; cc < 2; ++cc) {
                unsigned c = (unsigned)(cc ? c1 : c0);
                float g = gumbel1(bits32(KT0, KT1, base + c));
                float2 d = upk(acc[2 * r + cc]);
                float v = g + __fdiv_rn(d.x + d.y, 0.1f);   // exact div by TEMP
                if ((int)c == s_src[r]) v = __int_as_float(0xff800000);
                if (v > bestV[r]) { bestV[r] = v; bestC[r] = (int)c; }
            }
        }
    }

    // reduce: warp shfl, then cross-warp via smem; ties -> lowest column index
#pragma unroll 1
    for (int r = 0; r < RPB; ++r) {
        float v = bestV[r]; int c = bestC[r];
#pragma unroll
        for (int off = 16; off; off >>= 1) {
            float v2 = __shfl_down_sync(0xffffffffu, v, off);
            int   c2 = __shfl_down_sync(0xffffffffu, c, off);
            if (v2 > v || (v2 == v && c2 < c)) { v = v2; c = c2; }
        }
        if (lane == 0) { redV[r][w] = v; redC[r][w] = c; }
    }
    __syncthreads();
    if (tid < RPB) {
        float v = redV[tid][0]; int c = redC[tid][0];
#pragma unroll
        for (int i = 1; i < 8; ++i) {
            float v2 = redV[tid][i]; int c2 = redC[tid][i];
            if (v2 > v || (v2 == v && c2 < c)) { v = v2; c = c2; }
        }
        if (tid < nrows) g_tgt[jb + tid] = c;
    }
}

// ===========================================================================
// Kernel 4: hard_negs[j] = alpha_j * z[src_j] + (1 - alpha_j) * z[tgt_j]
// ===========================================================================
__global__ void k_out(const float* __restrict__ z, float* __restrict__ out) {
    int j = blockIdx.x, t = threadIdx.x;
    float a = g_alpha[j];
    int   s = g_src[j], g = g_tgt[j];
    out[j * D_K + t] = a * z[s * D_K + t] + (1.0f - a) * z[g * D_K + t];
}

// ===========================================================================
extern "C" void kernel_launch(void* const* d_in, const int* in_sizes, int n_in,
                              void* d_out, int out_size) {
    (void)in_sizes; (void)n_in; (void)out_size;
    const float* z  = (const float*)d_in[0];
    float* out      = (float*)d_out;

    k_norm  <<<B_N, 256>>>(z);
    k_rng   <<<(NHARD + 255) / 256, 256>>>();
    k_argmax<<<NBLK, 256>>>();
    k_out   <<<NHARD, 256>>>(z, out);
}

// round 12
// speedup vs baseline: 1.1337x; 1.1337x over previous
#include <cuda_runtime.h>
#include <cuda_bf16.h>
#include <cstdint>

// ---------------------------------------------------------------------------
// HardNegativeMiner: bit-exact replication of jax.random, PARTITIONABLE
// threefry mode (JAX default):
//   split(key,n):  key_i  = threefry(key, (0, i))
//   bits32 at flat index i = out0 ^ out1 of threefry(key, 0, i)
//   randint(key,...): k1,k2 = split(key); span=2^14 power of two ->
//                     result = bits32(k2, j) & 0x3FFF       (int32, x64 off)
//   B=16384, D=256, n_hard=3276, TEMPERATURE=0.1, MIX_ALPHA=0.5
// ---------------------------------------------------------------------------

#define B_N   16384
#define D_K   256
#define NHARD 3276
#define RPB   24                // rows per block in the argmax kernel
#define NBLK  137               // ceil(3276 / 24)

// ------------------- scratch (static device memory only) -------------------
__device__ float g_znT[D_K * B_N];   // z_norm transposed: [k][c]  (16 MB)
__device__ int   g_src[NHARD];
__device__ int   g_tgt[NHARD];
__device__ float g_alpha[NHARD];

// ---------------- compile-time threefry for key derivation -----------------
struct U2c { unsigned a, b; };
constexpr unsigned rotl32c(unsigned v, int d) { return (v << d) | (v >> (32 - d)); }
constexpr U2c tf_const(unsigned k0, unsigned k1, unsigned x0, unsigned x1) {
    unsigned ks[3] = { k0, k1, k0 ^ k1 ^ 0x1BD11BDAu };
    x0 += ks[0]; x1 += ks[1];
    const int rotA[4] = {13, 15, 26, 6};
    const int rotB[4] = {17, 29, 16, 24};
    for (int g = 0; g < 5; ++g) {
        const int* R = (g % 2 == 0) ? rotA : rotB;
        for (int i = 0; i < 4; ++i) { x0 += x1; x1 = rotl32c(x1, R[i]); x1 ^= x0; }
        x0 += ks[(g + 1) % 3];
        x1 += ks[(g + 2) % 3] + (unsigned)(g + 1);
    }
    return U2c{ x0, x1 };
}
// jax.random.key(42) -> (0,42). Partitionable split: key_i = tf(key, 0, i).
constexpr U2c KSRC = tf_const(0u, 42u, 0u, 0u);   // k_src   = split(key,3)[0]
constexpr U2c KTGT = tf_const(0u, 42u, 0u, 1u);   // k_tgt   = split(key,3)[1]
constexpr U2c KALP = tf_const(0u, 42u, 0u, 2u);   // k_alpha = split(key,3)[2]
// randint's INTERNAL split: k1,k2 = split(k_src); lower_bits uses k2.
constexpr U2c KSL  = tf_const(KSRC.a, KSRC.b, 0u, 1u);
constexpr unsigned KL0 = KSL.a,  KL1 = KSL.b;     // randint lower-bits key
constexpr unsigned KT0 = KTGT.a, KT1 = KTGT.b;
constexpr unsigned KA0 = KALP.a, KA1 = KALP.b;

// ------------------------- device threefry2x32-20 --------------------------
__device__ __forceinline__ uint2 tf2x32(unsigned k0, unsigned k1,
                                        unsigned x0, unsigned x1) {
    unsigned k2 = k0 ^ k1 ^ 0x1BD11BDAu;
    x0 += k0; x1 += k1;
#define TF_R4(a,b,c,d) \
    x0 += x1; x1 = __funnelshift_l(x1, x1, a); x1 ^= x0; \
    x0 += x1; x1 = __funnelshift_l(x1, x1, b); x1 ^= x0; \
    x0 += x1; x1 = __funnelshift_l(x1, x1, c); x1 ^= x0; \
    x0 += x1; x1 = __funnelshift_l(x1, x1, d); x1 ^= x0;
    TF_R4(13,15,26,6);   x0 += k1; x1 += k2 + 1u;
    TF_R4(17,29,16,24);  x0 += k2; x1 += k0 + 2u;
    TF_R4(13,15,26,6);   x0 += k0; x1 += k1 + 3u;
    TF_R4(17,29,16,24);  x0 += k1; x1 += k2 + 4u;
    TF_R4(13,15,26,6);   x0 += k2; x1 += k0 + 5u;
#undef TF_R4
    return make_uint2(x0, x1);
}
// partitionable 32-bit random bits at flat index i (hi word of 64-bit iota = 0)
__device__ __forceinline__ unsigned bits32(unsigned k0, unsigned k1, unsigned i) {
    uint2 o = tf2x32(k0, k1, 0u, i);
    return o.x ^ o.y;
}

// ---------------- accurate logf (cephes, fast-math-immune) -----------------
// valid for positive normal inputs (all our inputs are in (5.9e-8, 88.8])
__device__ __forceinline__ float alog(float x) {
    int ix = __float_as_int(x);
    int e  = ((ix >> 23) & 0xff) - 126;
    float m = __int_as_float((ix & 0x007fffff) | 0x3f000000);  // [0.5, 1)
    if (m < 0.70710678f) { m = m + m; e -= 1; }                // [~0.707, ~1.414)
    float u = m - 1.0f;
    float z = u * u;
    float p =             7.0376836292e-2f;
    p = fmaf(p, u, -1.1514610310e-1f);
    p = fmaf(p, u,  1.1676998740e-1f);
    p = fmaf(p, u, -1.2420140846e-1f);
    p = fmaf(p, u,  1.4249322787e-1f);
    p = fmaf(p, u, -1.6668057665e-1f);
    p = fmaf(p, u,  2.0000714765e-1f);
    p = fmaf(p, u, -2.4999993993e-1f);
    p = fmaf(p, u,  3.3333331174e-1f);
    float y  = u * z * p;
    float fe = (float)e;
    y = fmaf(fe, -2.12194440e-4f, y);
    y = fmaf(-0.5f, z, y);
    float r = u + y;
    r = fmaf(fe, 0.693359375f, r);
    return r;
}

// uniform bits -> float in [0,1): jax mantissa trick
__device__ __forceinline__ float u01(unsigned bits) {
    return __uint_as_float((bits >> 9) | 0x3f800000u) - 1.0f;
}
// gumbel: -log(-log(max(tiny, u)))   (tiny = FLT_MIN; matches jax uniform clamp)
__device__ __forceinline__ float gumbel1(unsigned bits) {
    float f = u01(bits);
    float u = fmaxf(f, 1.17549435e-38f);
    float t = -alog(u);
    return -alog(t);
}

// --------------------------- f32x2 packed FMA ------------------------------
__device__ __forceinline__ unsigned long long pk(float lo, float hi) {
    unsigned long long r;
    asm("mov.b64 %0, {%1, %2};" : "=l"(r) : "f"(lo), "f"(hi));
    return r;
}
__device__ __forceinline__ float2 upk(unsigned long long v) {
    float2 f;
    asm("mov.b64 {%0, %1}, %2;" : "=f"(f.x), "=f"(f.y) : "l"(v));
    return f;
}
__device__ __forceinline__ void ffma2(unsigned long long& d,
                                      unsigned long long a,
                                      unsigned long long b) {
    asm("fma.rn.f32x2 %0, %1, %2, %0;" : "+l"(d) : "l"(a), "l"(b));
}

// ===========================================================================
// Kernel 1: L2-normalize rows of z, store TRANSPOSED via smem tile transpose
//   (coalesced 128B stores; padded smem banks). 512 blocks x 32 rows.
// ===========================================================================
__global__ void __launch_bounds__(256) k_norm(const float* __restrict__ z) {
    __shared__ float zs[32][257];
    const int tid = threadIdx.x, lane = tid & 31, w = tid >> 5;
    const int row0 = blockIdx.x * 32;

#pragma unroll
    for (int i = 0; i < 4; ++i) {
        int r    = w * 4 + i;          // local row 0..31
        int grow = row0 + r;
        float v[8]; float ss = 0.0f;
#pragma unroll
        for (int k8 = 0; k8 < 8; ++k8) {
            v[k8] = z[grow * D_K + k8 * 32 + lane];
            ss = fmaf(v[k8], v[k8], ss);
        }
#pragma unroll
        for (int o = 16; o; o >>= 1) ss += __shfl_xor_sync(0xffffffffu, ss, o);
        float nrm = fmaxf(sqrtf(ss), 1e-12f);
#pragma unroll
        for (int k8 = 0; k8 < 8; ++k8)
            zs[r][k8 * 32 + lane] = __fdiv_rn(v[k8], nrm);
    }
    __syncthreads();

    // warp w writes k in [w*32, w*32+32); lanes cover 32 consecutive columns
#pragma unroll 4
    for (int kk = 0; kk < 32; ++kk) {
        int k = w * 32 + kk;
        g_znT[k * B_N + row0 + lane] = zs[lane][k];
    }
}

// ===========================================================================
// Kernel 2: src indices (randint int32 w/ internal split) + alpha (f32 * 0.5)
// ===========================================================================
__global__ void k_rng() {
    int j = blockIdx.x * 256 + threadIdx.x;
    if (j < NHARD) {
        g_src[j]   = (int)(bits32(KL0, KL1, (unsigned)j) & (B_N - 1));
        g_alpha[j] = u01(bits32(KA0, KA1, (unsigned)j)) * 0.5f;
    }
}

// ===========================================================================
// Kernel 3: per sampled row j, tgt[j] = argmax_c [ gumbel(j,c) + sim(src_j,c)/0.1 ]
//   24 rows/block. The 48 gumbels per column-iteration are INTERLEAVED into
//   the first 48 of the 64 k-chunk FMA iterations (staged in smem) so the
//   threefry ALU work hides inside the fma-pipe shadow instead of running
//   as a serial epilogue phase.
// ===========================================================================
__global__ void __launch_bounds__(256, 1) k_argmax() {
    __shared__ __align__(16) float sA[RPB * 256];   // 24 KB A-tile
    __shared__ float sG[48 * 256];                  // 48 KB gumbel staging
    __shared__ int   s_src[RPB];
    __shared__ float redV[RPB][8];
    __shared__ int   redC[RPB][8];

    const int tid  = threadIdx.x;
    const int lane = tid & 31, w = tid >> 5;
    const int jb = blockIdx.x * RPB;
    const int nrows = min(RPB, NHARD - jb);

    if (tid < RPB) s_src[tid] = (tid < nrows) ? g_src[jb + tid] : 0;
    __syncthreads();

    // fill A-tile: row r = z_norm[src_{jb+r}] (gathered from transposed layout)
#pragma unroll 1
    for (int r = 0; r < RPB; ++r)
        sA[r * 256 + tid] = g_znT[tid * B_N + s_src[r]];
    __syncthreads();

    const ulonglong2* sAv = reinterpret_cast<const ulonglong2*>(sA);

    float bestV[RPB]; int bestC[RPB];
#pragma unroll
    for (int r = 0; r < RPB; ++r) { bestV[r] = __int_as_float(0xff800000); bestC[r] = 0; }

    for (int it = 0; it < 32; ++it) {
        const int c0 = it * 512 + w * 64 + lane;   // lanes -> consecutive cols
        const int c1 = c0 + 32;

        unsigned long long acc[2 * RPB];            // [row][col 0..1]
#pragma unroll
        for (int i = 0; i < 2 * RPB; ++i) acc[i] = 0ull;

        const float* pb0 = g_znT + c0;
        const float* pb1 = g_znT + c1;

        // ---- phase 1: kc 0..47, FMA block + one interleaved gumbel each ----
#pragma unroll 1
        for (int kc = 0; kc < 48; ++kc) {
            float x0 = pb0[0], x1 = pb0[B_N], x2 = pb0[2 * B_N], x3 = pb0[3 * B_N];
            float y0 = pb1[0], y1 = pb1[B_N], y2 = pb1[2 * B_N], y3 = pb1[3 * B_N];
            pb0 += 4 * B_N; pb1 += 4 * B_N;
            unsigned long long bl0 = pk(x0, x1), bh0 = pk(x2, x3);
            unsigned long long bl1 = pk(y0, y1), bh1 = pk(y2, y3);
#pragma unroll
            for (int r = 0; r < RPB; ++r) {
                ulonglong2 a = sAv[r * 64 + kc];   // LDS.128 broadcast
                ffma2(acc[2 * r + 0], a.x, bl0);
                ffma2(acc[2 * r + 0], a.y, bh0);
                ffma2(acc[2 * r + 1], a.x, bl1);
                ffma2(acc[2 * r + 1], a.y, bh1);
            }
            // interleaved gumbel for slot kc: r = kc>>1, cc = kc&1
            {
                int gr = kc >> 1;
                unsigned gc = (unsigned)((kc & 1) ? c1 : c0);
                unsigned idx = (unsigned)(jb + gr) * (unsigned)B_N + gc;
                sG[kc * 256 + tid] = gumbel1(bits32(KT0, KT1, idx));
            }
        }
        // ---- phase 2: kc 48..63, FMA only ----
#pragma unroll 1
        for (int kc = 48; kc < 64; ++kc) {
            float x0 = pb0[0], x1 = pb0[B_N], x2 = pb0[2 * B_N], x3 = pb0[3 * B_N];
            float y0 = pb1[0], y1 = pb1[B_N], y2 = pb1[2 * B_N], y3 = pb1[3 * B_N];
            pb0 += 4 * B_N; pb1 += 4 * B_N;
            unsigned long long bl0 = pk(x0, x1), bh0 = pk(x2, x3);
            unsigned long long bl1 = pk(y0, y1), bh1 = pk(y2, y3);
#pragma unroll
            for (int r = 0; r < RPB; ++r) {
                ulonglong2 a = sAv[r * 64 + kc];
                ffma2(acc[2 * r + 0], a.x, bl0);
                ffma2(acc[2 * r + 0], a.y, bh0);
                ffma2(acc[2 * r + 1], a.x, bl1);
                ffma2(acc[2 * r + 1], a.y, bh1);
            }
        }

        // ---- combine: staged gumbel + logits, running argmax ----
#pragma unroll
        for (int s = 0; s < 48; ++s) {
            int r  = s >> 1;
            int cc = s & 1;
            int c  = cc ? c1 : c0;
            float g  = sG[s * 256 + tid];
            float2 d = upk(acc[2 * r + cc]);
            float v  = g + __fdiv_rn(d.x + d.y, 0.1f);   // exact div by TEMP
            if (c == s_src[r]) v = __int_as_float(0xff800000);
            if (v > bestV[r]) { bestV[r] = v; bestC[r] = c; }
        }
    }

    // reduce: warp shfl, then cross-warp via smem; ties -> lowest column index
#pragma unroll 1
    for (int r = 0; r < RPB; ++r) {
        float v = bestV[r]; int c = bestC[r];
#pragma unroll
        for (int off = 16; off; off >>= 1) {
            float v2 = __shfl_down_sync(0xffffffffu, v, off);
            int   c2 = __shfl_down_sync(0xffffffffu, c, off);
            if (v2 > v || (v2 == v && c2 < c)) { v = v2; c = c2; }
        }
        if (lane == 0) { redV[r][w] = v; redC[r][w] = c; }
    }
    __syncthreads();
    if (tid < RPB) {
        float v = redV[tid][0]; int c = redC[tid][0];
#pragma unroll
        for (int i = 1; i < 8; ++i) {
            float v2 = redV[tid][i]; int c2 = redC[tid][i];
            if (v2 > v || (v2 == v && c2 < c)) { v = v2; c = c2; }
        }
        if (tid < nrows) g_tgt[jb + tid] = c;
    }
}

// ===========================================================================
// Kernel 4: hard_negs[j] = alpha_j * z[src_j] + (1 - alpha_j) * z[tgt_j]
// ===========================================================================
__global__ void k_out(const float* __restrict__ z, float* __restrict__ out) {
    int j = blockIdx.x, t = threadIdx.x;
    float a = g_alpha[j];
    int   s = g_src[j], g = g_tgt[j];
    out[j * D_K + t] = a * z[s * D_K + t] + (1.0f - a) * z[g * D_K + t];
}

// ===========================================================================
extern "C" void kernel_launch(void* const* d_in, const int* in_sizes, int n_in,
                              void* d_out, int out_size) {
    (void)in_sizes; (void)n_in; (void)out_size;
    const float* z  = (const float*)d_in[0];
    float* out      = (float*)d_out;

    k_norm  <<<B_N / 32, 256>>>(z);
    k_rng   <<<(NHARD + 255) / 256, 256>>>();
    k_argmax<<<NBLK, 256>>>();
    k_out   <<<NHARD, 256>>>(z, out);
}